// round 6
// baseline (speedup 1.0000x reference)
#include <cuda_runtime.h>

// PositionalEncoding: out[b,t,i] = x[b,t,i] + P[t,i]
//   P[2f,   i] = sin(f / 10000^(2i/F))
//   P[2f+1, i] = cos(f / 10000^(2i/F))
// x: [32, 2048, 1024] fp32. HBM-streaming-bound (512MB floor).
// R5 = R1 champion config (256 thr, occ cap 4 -> 64-reg budget -> 8 LDG.128
// in flight, unroll 8, default caching) + persistent grid-stride over rows
// (592 CTAs = 148 SMs x 4) to eliminate wave-transition gaps and the
// partial last wave.

#define PE_T 2048
#define PE_F 1024
#define PE_B 32
#define PE_GRID 592   // 148 SMs * 4 CTAs/SM

__global__ __launch_bounds__(256, 4)
void pe_add_kernel(const float* __restrict__ x, float* __restrict__ out) {
    const int c = threadIdx.x;         // float4 column 0..255
    const float4* __restrict__ x4 = (const float4*)x;
    float4* __restrict__ o4 = (float4*)out;
    const size_t row_stride4 = (size_t)PE_T * (PE_F / 4);   // float4 per batch slice

    for (int t = blockIdx.x; t < PE_T; t += PE_GRID) {
        const float f = (float)(t >> 1);
        const bool is_sin = (t & 1) == 0;

        float pv[4];
#pragma unroll
        for (int k = 0; k < 4; k++) {
            const int i = c * 4 + k;
            const float e = (float)i * (1.0f / 512.0f);   // 2*i/F, exact in fp32
            const float den = powf(10000.0f, e);
            const float ang = f / den;
            pv[k] = is_sin ? sinf(ang) : cosf(ang);
        }
        const float4 p = make_float4(pv[0], pv[1], pv[2], pv[3]);

        const size_t base = (size_t)t * (PE_F / 4) + (size_t)c;

#pragma unroll 8
        for (int b = 0; b < PE_B; b++) {
            const size_t idx = base + (size_t)b * row_stride4;
            float4 v = x4[idx];
            v.x += p.x;
            v.y += p.y;
            v.z += p.z;
            v.w += p.w;
            o4[idx] = v;
        }
    }
}

extern "C" void kernel_launch(void* const* d_in, const int* in_sizes, int n_in,
                              void* d_out, int out_size) {
    const float* x = (const float*)d_in[0];
    float* out = (float*)d_out;
    pe_add_kernel<<<PE_GRID, 256>>>(x, out);
}

// round 7
// speedup vs baseline: 1.2265x; 1.2265x over previous
#include <cuda_runtime.h>

// PositionalEncoding: out[b,t,i] = x[b,t,i] + P[t,i]
//   P[2f,   i] = sin(f / 10000^(2i/F))
//   P[2f+1, i] = cos(f / 10000^(2i/F))
// x: [32, 2048, 1024] fp32. HBM-streaming-bound (512MB floor).
// R6 = R1 champion micro-config EXACTLY (256 thr, occ cap 4 -> 48 regs,
// float4, default caching, unroll 8) with ONE change: batch loop split in
// half across blockIdx.y (grid 2048x2, 16 batches/thread) to shrink the
// wave-quantization tail (3.46 waves @46%-full tail -> 6.92 waves @92%).

#define PE_T 2048
#define PE_F 1024
#define PE_B 32
#define PE_BY 2                      // batch split factor
#define PE_BPER (PE_B / PE_BY)       // 16 batches per thread

__global__ __launch_bounds__(256, 4)
void pe_add_kernel(const float* __restrict__ x, float* __restrict__ out) {
    const int t = blockIdx.x;          // row 0..2047
    const int c = threadIdx.x;         // float4 column 0..255
    const int b0 = blockIdx.y * PE_BPER;

    const float f = (float)(t >> 1);
    const bool is_sin = (t & 1) == 0;

    float pv[4];
#pragma unroll
    for (int k = 0; k < 4; k++) {
        const int i = c * 4 + k;
        const float e = (float)i * (1.0f / 512.0f);   // 2*i/F, exact in fp32
        const float den = powf(10000.0f, e);
        const float ang = f / den;
        pv[k] = is_sin ? sinf(ang) : cosf(ang);
    }
    const float4 p = make_float4(pv[0], pv[1], pv[2], pv[3]);

    const float4* __restrict__ x4 = (const float4*)x;
    float4* __restrict__ o4 = (float4*)out;
    const size_t row_stride4 = (size_t)PE_T * (PE_F / 4);   // float4 per batch slice
    const size_t base = (size_t)t * (PE_F / 4) + (size_t)c
                      + (size_t)b0 * row_stride4;

#pragma unroll 8
    for (int b = 0; b < PE_BPER; b++) {
        const size_t idx = base + (size_t)b * row_stride4;
        float4 v = x4[idx];
        v.x += p.x;
        v.y += p.y;
        v.z += p.z;
        v.w += p.w;
        o4[idx] = v;
    }
}

extern "C" void kernel_launch(void* const* d_in, const int* in_sizes, int n_in,
                              void* d_out, int out_size) {
    const float* x = (const float*)d_in[0];
    float* out = (float*)d_out;
    dim3 grid(PE_T, PE_BY);
    pe_add_kernel<<<grid, 256>>>(x, out);
}

// round 9
// speedup vs baseline: 1.2488x; 1.0182x over previous
#include <cuda_runtime.h>

// PositionalEncoding: out[b,t,i] = x[b,t,i] + P[t,i]
//   P[2f,   i] = sin(f / 10000^(2i/F))
//   P[2f+1, i] = cos(f / 10000^(2i/F))
// x: [32, 2048, 1024] fp32. HBM-streaming-bound (512MB floor).
// R7 = R6 (champion: 256 thr, occ cap 4, float4, BY=2 batch split) +
// software pipeline: first 8 LDG.128s issue BEFORE the sin/cos MUFU chain
// (no dependence), hiding the per-CTA transcendental prologue under the
// first memory burst. Second half of batches loads while first half stores.

#define PE_T 2048
#define PE_F 1024
#define PE_B 32
#define PE_BY 2                      // batch split factor
#define PE_BPER (PE_B / PE_BY)       // 16 batches per thread
#define PE_H (PE_BPER / 2)           // 8 per pipeline half

__global__ __launch_bounds__(256, 4)
void pe_add_kernel(const float* __restrict__ x, float* __restrict__ out) {
    const int t = blockIdx.x;          // row 0..2047
    const int c = threadIdx.x;         // float4 column 0..255
    const int b0 = blockIdx.y * PE_BPER;

    const float4* __restrict__ x4 = (const float4*)x;
    float4* __restrict__ o4 = (float4*)out;
    const size_t row_stride4 = (size_t)PE_T * (PE_F / 4);   // float4 per batch slice
    const size_t base = (size_t)t * (PE_F / 4) + (size_t)c
                      + (size_t)b0 * row_stride4;

    // ---- Pipeline stage 1: issue first 8 loads (independent of P) ----
    float4 buf[PE_H];
#pragma unroll
    for (int b = 0; b < PE_H; b++)
        buf[b] = x4[base + (size_t)b * row_stride4];

    // ---- Compute P while loads are in flight ----
    const float f = (float)(t >> 1);
    const bool is_sin = (t & 1) == 0;
    float pv[4];
#pragma unroll
    for (int k = 0; k < 4; k++) {
        const int i = c * 4 + k;
        const float e = (float)i * (1.0f / 512.0f);   // 2*i/F, exact in fp32
        const float den = powf(10000.0f, e);
        const float ang = f / den;
        pv[k] = is_sin ? sinf(ang) : cosf(ang);
    }
    const float4 p = make_float4(pv[0], pv[1], pv[2], pv[3]);

    // ---- Stage 2: issue second-half loads, then drain first half ----
    float4 buf2[PE_H];
#pragma unroll
    for (int b = 0; b < PE_H; b++)
        buf2[b] = x4[base + (size_t)(b + PE_H) * row_stride4];

#pragma unroll
    for (int b = 0; b < PE_H; b++) {
        float4 v = buf[b];
        v.x += p.x; v.y += p.y; v.z += p.z; v.w += p.w;
        o4[base + (size_t)b * row_stride4] = v;
    }

#pragma unroll
    for (int b = 0; b < PE_H; b++) {
        float4 v = buf2[b];
        v.x += p.x; v.y += p.y; v.z += p.z; v.w += p.w;
        o4[base + (size_t)(b + PE_H) * row_stride4] = v;
    }
}

extern "C" void kernel_launch(void* const* d_in, const int* in_sizes, int n_in,
                              void* d_out, int out_size) {
    const float* x = (const float*)d_in[0];
    float* out = (float*)d_out;
    dim3 grid(PE_T, PE_BY);
    pe_add_kernel<<<grid, 256>>>(x, out);
}